// round 6
// baseline (speedup 1.0000x reference)
#include <cuda_runtime.h>
#include <cuda_fp16.h>
#include <math.h>
#include <limits.h>

#define NN   50000
#define EE   800000
#define GG   512
#define HH   4
#define CC   64
#define HC   256      // H*C
#define DIN_ 128
#define DENC_ 256

#define MTILES 391          // (NN+127)/128
#define SCAT_BLOCKS 3125    // (EE+255)/256
#define GEMM_BLOCKS (MTILES * 4 * 2)
#define HIST_BLOCKS ((EE + 1023) / 1024)

// ---------------- scratch (static device arrays; no allocation) ----------------
__device__ __half g_xl[NN * HC];     // 25.6 MB (fp16 node features, source)
__device__ __half g_xr[NN * HC];     // 25.6 MB (fp16 node features, target)
__device__ __half g_xh[NN * DIN_];   // 12.8 MB (fp16 input features)
__device__ __half g_whl[DIN_ * HC];  // fp16 weights
__device__ __half g_whr[DIN_ * HC];
__device__ int   g_deg[NN];          // in-degree histogram (real edges only)
__device__ int   g_off[NN + 1];      // CSR row offsets
__device__ int   g_woff[NN];         // working copy for scatter
__device__ int   g_csrc[EE];         // CSR: src node per incoming edge
__device__ float g_pool[GG * CC];    // per-graph sums
__device__ int   g_cnt[GG];          // per-graph node counts
__device__ unsigned g_done;          // hist block completion counter

// ---------------- mma helpers ----------------
__device__ __forceinline__ unsigned smem_u32(const void* p) {
    return (unsigned)__cvta_generic_to_shared(p);
}
__device__ __forceinline__ void ldm_x4(unsigned& r0, unsigned& r1, unsigned& r2,
                                       unsigned& r3, unsigned addr) {
    asm volatile("ldmatrix.sync.aligned.m8n8.x4.shared.b16 {%0,%1,%2,%3}, [%4];"
                 : "=r"(r0), "=r"(r1), "=r"(r2), "=r"(r3) : "r"(addr));
}
__device__ __forceinline__ void ldm_x4_t(unsigned& r0, unsigned& r1, unsigned& r2,
                                         unsigned& r3, unsigned addr) {
    asm volatile("ldmatrix.sync.aligned.m8n8.x4.trans.shared.b16 {%0,%1,%2,%3}, [%4];"
                 : "=r"(r0), "=r"(r1), "=r"(r2), "=r"(r3) : "r"(addr));
}
__device__ __forceinline__ void mma16816(float* d, const unsigned* a, const unsigned* b) {
    asm volatile(
        "mma.sync.aligned.m16n8k16.row.col.f32.f16.f16.f32 "
        "{%0,%1,%2,%3}, {%4,%5,%6,%7}, {%8,%9}, {%0,%1,%2,%3};"
        : "+f"(d[0]), "+f"(d[1]), "+f"(d[2]), "+f"(d[3])
        : "r"(a[0]), "r"(a[1]), "r"(a[2]), "r"(a[3]), "r"(b[0]), "r"(b[1]));
}

// ---------------- L1: convert to fp16 + zero scratch ----------------
__global__ void k_cvt(const float* __restrict__ x,
                      const float* __restrict__ Wl,
                      const float* __restrict__ Wr) {
    int i = blockIdx.x * blockDim.x + threadIdx.x;
    int stride = gridDim.x * blockDim.x;
    if (i == 0) g_done = 0u;
    for (int j = i; j < NN; j += stride) g_deg[j] = 0;
    for (int j = i; j < GG * CC; j += stride) g_pool[j] = 0.f;
    for (int j = i; j < GG; j += stride) g_cnt[j] = 0;
    for (int j = i; j < NN * DIN_ / 2; j += stride) {
        float2 v = ((const float2*)x)[j];
        ((__half2*)g_xh)[j] = __floats2half2_rn(v.x, v.y);
    }
    for (int j = i; j < DIN_ * HC / 2; j += stride) {
        float2 a = ((const float2*)Wl)[j];
        float2 b = ((const float2*)Wr)[j];
        ((__half2*)g_whl)[j] = __floats2half2_rn(a.x, a.y);
        ((__half2*)g_whr)[j] = __floats2half2_rn(b.x, b.y);
    }
}

// ---------------- L2: histogram + (last block) exclusive scan ----------------
__global__ __launch_bounds__(1024) void k_hist_scan(const int* __restrict__ ei) {
    int t = blockIdx.x * 1024 + threadIdx.x;
    if (t < EE) atomicAdd(&g_deg[ei[EE + t]], 1);

    // completion: last block performs the scan
    __threadfence();
    __syncthreads();
    __shared__ bool s_last;
    if (threadIdx.x == 0) {
        unsigned prev = atomicAdd(&g_done, 1u);
        s_last = (prev == (unsigned)(gridDim.x - 1));
    }
    __syncthreads();
    if (!s_last) return;
    __threadfence();   // acquire all histogram updates

    __shared__ int warpsum[32];
    const int tid = threadIdx.x;
    const int per = (NN + 1023) / 1024;   // 49
    const int base = tid * per;
    int sum = 0;
    for (int i = 0; i < per; i++) {
        int idx = base + i;
        if (idx < NN) sum += g_deg[idx];
    }
    const int lane = tid & 31, wid = tid >> 5;
    int v = sum;
#pragma unroll
    for (int off = 1; off < 32; off <<= 1) {
        int u = __shfl_up_sync(0xffffffffu, v, off);
        if (lane >= off) v += u;
    }
    if (lane == 31) warpsum[wid] = v;
    __syncthreads();
    if (wid == 0) {
        int wv = warpsum[lane];
#pragma unroll
        for (int off = 1; off < 32; off <<= 1) {
            int u = __shfl_up_sync(0xffffffffu, wv, off);
            if (lane >= off) wv += u;
        }
        warpsum[lane] = wv;
    }
    __syncthreads();
    int excl = v - sum + (wid > 0 ? warpsum[wid - 1] : 0);
    int run = excl;
    for (int i = 0; i < per; i++) {
        int idx = base + i;
        if (idx < NN) {
            int c = g_deg[idx];
            g_off[idx] = run;
            g_woff[idx] = run;
            run += c;
        }
    }
    if (tid == 1023) g_off[NN] = run;
}

// ---------------- L3: fused CSR-scatter + tensor-core GEMM ----------------
__global__ __launch_bounds__(256) void k_mid(const float* __restrict__ bl,
                                             const float* __restrict__ br,
                                             const int* __restrict__ ei) {
    __shared__ __half sA[128 * 128];  // 32 KB
    __shared__ __half sB[128 * 64];   // 16 KB

    const int tid = threadIdx.x;
    int fb = blockIdx.x;

    if (fb < SCAT_BLOCKS) {           // ---- scatter part ----
        int t = fb * 256 + tid;
        if (t < EE) {
            int dst = ei[EE + t];
            int pos = atomicAdd(&g_woff[dst], 1);
            g_csrc[pos] = ei[t];
        }
        return;
    }
    fb -= SCAT_BLOCKS;                // ---- gemm part ----
    const int mb = fb % MTILES;
    const int rest = fb / MTILES;
    const int nb = rest & 3;
    const int z = rest >> 2;

    const __half* W   = z ? g_whr : g_whl;
    const float* bias = z ? br : bl;
    __half* out       = z ? g_xr : g_xl;
    const int bm = mb * 128, bn = nb * 64;

#pragma unroll
    for (int it = 0; it < 8; it++) {
        int q = it * 256 + tid;
        int row = q >> 4, cc = q & 15;
        int gm = bm + row;
        uint4 v = make_uint4(0u, 0u, 0u, 0u);
        if (gm < NN) v = *(const uint4*)&g_xh[gm * DIN_ + cc * 8];
        *(uint4*)&sA[row * 128 + ((cc ^ (row & 7)) << 3)] = v;
    }
#pragma unroll
    for (int it = 0; it < 4; it++) {
        int q = it * 256 + tid;
        int row = q >> 3, cc = q & 7;
        uint4 v = *(const uint4*)&W[row * HC + bn + cc * 8];
        *(uint4*)&sB[row * 64 + ((cc ^ (row & 7)) << 3)] = v;
    }
    __syncthreads();

    const int wid = tid >> 5, lane = tid & 31;
    const int wm = (wid & 3) * 32;
    const int wn = (wid >> 2) * 32;

    float acc[2][4][4];
#pragma unroll
    for (int i = 0; i < 2; i++)
#pragma unroll
        for (int j = 0; j < 4; j++)
#pragma unroll
            for (int k = 0; k < 4; k++) acc[i][j][k] = 0.f;

#pragma unroll
    for (int ks = 0; ks < 8; ks++) {
        const int k0 = ks * 16;
        unsigned a[2][4], b[4][2];
#pragma unroll
        for (int am = 0; am < 2; am++) {
            int row = wm + am * 16 + (lane & 15);
            int cc = (k0 >> 3) + (lane >> 4);
            unsigned addr = smem_u32(&sA[row * 128 + ((cc ^ (row & 7)) << 3)]);
            ldm_x4(a[am][0], a[am][1], a[am][2], a[am][3], addr);
        }
#pragma unroll
        for (int bt = 0; bt < 2; bt++) {
            int row = k0 + (lane & 15);
            int cc = ((wn + bt * 16) >> 3) + (lane >> 4);
            unsigned addr = smem_u32(&sB[row * 64 + ((cc ^ (row & 7)) << 3)]);
            unsigned r0, r1, r2, r3;
            ldm_x4_t(r0, r1, r2, r3, addr);
            b[bt * 2 + 0][0] = r0; b[bt * 2 + 0][1] = r1;
            b[bt * 2 + 1][0] = r2; b[bt * 2 + 1][1] = r3;
        }
#pragma unroll
        for (int am = 0; am < 2; am++)
#pragma unroll
            for (int bt = 0; bt < 4; bt++) mma16816(acc[am][bt], a[am], b[bt]);
    }

#pragma unroll
    for (int am = 0; am < 2; am++) {
        int row0 = bm + wm + am * 16 + (lane >> 2);
#pragma unroll
        for (int bt = 0; bt < 4; bt++) {
            int col = bn + wn + bt * 8 + (lane & 3) * 2;
            float b0 = bias[col], b1 = bias[col + 1];
            if (row0 < NN)
                *(__half2*)&out[row0 * HC + col] =
                    __floats2half2_rn(acc[am][bt][0] + b0, acc[am][bt][1] + b1);
            if (row0 + 8 < NN)
                *(__half2*)&out[(row0 + 8) * HC + col] =
                    __floats2half2_rn(acc[am][bt][2] + b0, acc[am][bt][3] + b1);
        }
    }
}

// ---------------- L4 (profiled): fused attention + aggregate + pool ------------
// leaky_relu(z, s) = max(z, s*z) for s<1: 2 ops per channel.
__global__ __launch_bounds__(256) void k_node(const float* __restrict__ att,
                                              const float* __restrict__ bgnn,
                                              const int* __restrict__ batch) {
    const int lane = threadIdx.x & 31;
    int w = (blockIdx.x * blockDim.x + threadIdx.x) >> 5;
    const int nw = (gridDim.x * blockDim.x) >> 5;

    const float4 at0 = *(const float4*)&att[lane * 8 + 0];
    const float4 at1 = *(const float4*)&att[lane * 8 + 4];

    for (int n = w; n < NN; n += nw) {
        uint4 ur = *(const uint4*)&g_xr[n * HC + lane * 8];
        const float2 r0 = __half22float2(*(__half2*)&ur.x);
        const float2 r1 = __half22float2(*(__half2*)&ur.y);
        const float2 r2 = __half22float2(*(__half2*)&ur.z);
        const float2 r3 = __half22float2(*(__half2*)&ur.w);

        float acc[8];
#pragma unroll
        for (int j = 0; j < 8; j++) acc[j] = 0.f;
        float D = 0.f;

        auto doedge = [&](uint4 ul) {
            const float2 l0 = __half22float2(*(__half2*)&ul.x);
            const float2 l1 = __half22float2(*(__half2*)&ul.y);
            const float2 l2 = __half22float2(*(__half2*)&ul.z);
            const float2 l3 = __half22float2(*(__half2*)&ul.w);
            float p = 0.f, z;
            z = l0.x + r0.x; p = fmaf(fmaxf(z, 0.2f * z), at0.x, p);
            z = l0.y + r0.y; p = fmaf(fmaxf(z, 0.2f * z), at0.y, p);
            z = l1.x + r1.x; p = fmaf(fmaxf(z, 0.2f * z), at0.z, p);
            z = l1.y + r1.y; p = fmaf(fmaxf(z, 0.2f * z), at0.w, p);
            z = l2.x + r2.x; p = fmaf(fmaxf(z, 0.2f * z), at1.x, p);
            z = l2.y + r2.y; p = fmaf(fmaxf(z, 0.2f * z), at1.y, p);
            z = l3.x + r3.x; p = fmaf(fmaxf(z, 0.2f * z), at1.z, p);
            z = l3.y + r3.y; p = fmaf(fmaxf(z, 0.2f * z), at1.w, p);
            p += __shfl_xor_sync(0xffffffffu, p, 4);
            p += __shfl_xor_sync(0xffffffffu, p, 2);
            p += __shfl_xor_sync(0xffffffffu, p, 1);
            const float a = __expf(p);
            D += a;
            acc[0] = fmaf(a, l0.x, acc[0]);
            acc[1] = fmaf(a, l0.y, acc[1]);
            acc[2] = fmaf(a, l1.x, acc[2]);
            acc[3] = fmaf(a, l1.y, acc[3]);
            acc[4] = fmaf(a, l2.x, acc[4]);
            acc[5] = fmaf(a, l2.y, acc[5]);
            acc[6] = fmaf(a, l3.x, acc[6]);
            acc[7] = fmaf(a, l3.y, acc[7]);
        };

        // self loop
        doedge(*(const uint4*)&g_xl[n * HC + lane * 8]);

        const int beg = g_off[n], end = g_off[n + 1];
        int e = beg;
        const int end4 = beg + ((end - beg) & ~3);
        for (; e < end4; e += 4) {
            const int s0 = g_csrc[e], s1 = g_csrc[e + 1];
            const int s2 = g_csrc[e + 2], s3 = g_csrc[e + 3];
            uint4 u0 = *(const uint4*)&g_xl[s0 * HC + lane * 8];
            uint4 u1 = *(const uint4*)&g_xl[s1 * HC + lane * 8];
            uint4 u2 = *(const uint4*)&g_xl[s2 * HC + lane * 8];
            uint4 u3 = *(const uint4*)&g_xl[s3 * HC + lane * 8];
            doedge(u0); doedge(u1); doedge(u2); doedge(u3);
        }
        for (; e < end; e++) {
            const int s = g_csrc[e];
            doedge(*(const uint4*)&g_xl[s * HC + lane * 8]);
        }

        const float inv = 1.f / (D + 1e-16f);
        float v[8];
#pragma unroll
        for (int j = 0; j < 8; j++) {
            float t = acc[j] * inv;
            t += __shfl_xor_sync(0xffffffffu, t, 8);
            t += __shfl_xor_sync(0xffffffffu, t, 16);
            v[j] = t;
        }

        if (lane < 8) {
            const int g = batch[n];
            if (lane == 0) atomicAdd(&g_cnt[g], 1);
#pragma unroll
            for (int j = 0; j < 8; j++) {
                const int c = lane * 8 + j;
                float val = fmaf(0.25f, v[j], bgnn[c]);
                val = fmaxf(val, 0.01f * val);   // outer leaky_relu(0.01)
                atomicAdd(&g_pool[g * CC + c], val);
            }
        }
    }
}

// ---------------- L5: final FC  out[g, :] = [hy[g], hg[g]] @ Wfc + bfc ----------
__global__ __launch_bounds__(256) void k_fc(const float* __restrict__ hy,
                                            const float* __restrict__ Wfc,
                                            const float* __restrict__ bfc,
                                            float* __restrict__ out) {
    const int g = blockIdx.x;
    const int j = threadIdx.x;
    __shared__ float sh[DENC_ + CC];
    sh[j] = hy[g * DENC_ + j];
    if (j < CC) {
        int c = g_cnt[g];
        float cn = c > 0 ? (float)c : 1.f;
        sh[DENC_ + j] = g_pool[g * CC + j] / cn;
    }
    __syncthreads();
    float acc = bfc[j];
#pragma unroll 8
    for (int k = 0; k < DENC_ + CC; k++)
        acc = fmaf(sh[k], Wfc[k * DENC_ + j], acc);
    out[g * DENC_ + j] = acc;
}

// ---------------- launch ----------------
extern "C" void kernel_launch(void* const* d_in, const int* in_sizes, int n_in,
                              void* d_out, int out_size) {
    const float* hy   = (const float*)d_in[0];
    const float* x    = (const float*)d_in[1];
    const int*   ei   = (const int*)d_in[2];
    const int*   batch= (const int*)d_in[3];
    const float* Wl   = (const float*)d_in[4];
    const float* bl   = (const float*)d_in[5];
    const float* Wr   = (const float*)d_in[6];
    const float* br   = (const float*)d_in[7];
    const float* att  = (const float*)d_in[8];
    const float* bgnn = (const float*)d_in[9];
    const float* Wfc  = (const float*)d_in[10];
    const float* bfc  = (const float*)d_in[11];
    float* out = (float*)d_out;

    k_cvt<<<512, 256>>>(x, Wl, Wr);                            // #1 cvt + zero
    k_hist_scan<<<HIST_BLOCKS, 1024>>>(ei);                    // #2 hist + scan
    k_mid<<<SCAT_BLOCKS + GEMM_BLOCKS, 256>>>(bl, br, ei);     // #3 scatter+gemm
    k_node<<<(NN / 8) + 1, 256>>>(att, bgnn, batch);           // #4 (profiled)
    k_fc<<<GG, 256>>>(hy, Wfc, bfc, out);                      // #5
}